// round 1
// baseline (speedup 1.0000x reference)
#include <cuda_runtime.h>
#include <math.h>

#define NB    8
#define NPK   80
#define NL    100000
#define NTOP  200
#define NANG  90
#define NM    (NTOP*NANG)
#define DIST  0.2f
#define EPSF  1e-12f

// ---- scratch (no allocation allowed) ----
__device__ int                g_score[NB * NL];
__device__ int                g_topidx[NB * NTOP];
__device__ float              g_cand[(size_t)NB * NM * 9];
__device__ unsigned long long g_best[NB];

// cofactor inverse matching the JAX reference (zero matrix if |det|<1e-10)
__device__ __forceinline__ void inv3(const float* M, float* o) {
    float a=M[0],b=M[1],c=M[2],d=M[3],e=M[4],f=M[5],g=M[6],h=M[7],i=M[8];
    float det = a*(e*i-f*h) - b*(d*i-f*g) + c*(d*h-e*g);
    float invd = (fabsf(det) >= 1e-10f) ? (1.0f/det) : 0.0f;
    o[0]=(e*i-f*h)*invd; o[1]=(c*h-b*i)*invd; o[2]=(b*f-c*e)*invd;
    o[3]=(f*g-d*i)*invd; o[4]=(a*i-c*g)*invd; o[5]=(c*d-a*f)*invd;
    o[6]=(d*h-e*g)*invd; o[7]=(b*g-a*h)*invd; o[8]=(a*e-b*d)*invd;
}

// ============================================================
// Kernel 1: per-(b,l) integer-ness score over the sphere lattice
// ============================================================
__global__ void k_score(const float* __restrict__ peaks,
                        const float* __restrict__ cell,
                        const float* __restrict__ lat) {
    __shared__ float sp[NB * NPK * 3];
    int tid = threadIdx.x;
    for (int i = tid; i < NB * NPK * 3; i += blockDim.x) sp[i] = peaks[i];
    if (blockIdx.x == 0 && tid < NB) g_best[tid] = 0ull;
    __syncthreads();

    int l = blockIdx.x * blockDim.x + tid;
    if (l >= NL) return;
    float lx = lat[l*3+0], ly = lat[l*3+1], lz = lat[l*3+2];
    float scale0 = sqrtf(cell[0]*cell[0] + cell[1]*cell[1] + cell[2]*cell[2]);

    for (int b = 0; b < NB; b++) {
        const float* pb = sp + b * NPK * 3;
        int cnt = 0;
        #pragma unroll 4
        for (int n = 0; n < NPK; n++) {
            float t = pb[n*3+0] * lx;
            t = fmaf(pb[n*3+1], ly, t);
            t = fmaf(pb[n*3+2], lz, t);
            float proj = t / scale0;          // keep true divide (match jnp)
            float fr = fabsf(proj - rintf(proj));
            cnt += (fr < DIST) ? 1 : 0;
        }
        g_score[b * NL + l] = cnt;
    }
}

// ============================================================
// Kernel 2: exact top-200 per batch with jax.lax.top_k tie semantics
//   (score descending, index ascending within equal scores)
// ============================================================
__global__ void k_topk() {
    int b = blockIdx.x;
    int tid = threadIdx.x;
    int lane = tid & 31, wid = tid >> 5;
    __shared__ int hist[96];
    __shared__ int warp_eq[32];
    __shared__ int sstar, snabove, sneq;
    __shared__ int cnt_above;
    __shared__ int sel[256];

    const int* sc = g_score + b * NL;
    if (tid < 96) hist[tid] = 0;
    if (tid == 0) cnt_above = 0;
    __syncthreads();
    for (int l = tid; l < NL; l += blockDim.x) atomicAdd(&hist[sc[l]], 1);
    __syncthreads();

    if (tid == 0) {
        int cum = 0, na = 0, s;
        for (s = 80; s >= 0; s--) {
            na = cum;            // strictly greater than s
            cum += hist[s];
            if (cum >= NTOP) break;
        }
        sstar = s; snabove = na; sneq = NTOP - na;
    }
    __syncthreads();
    int ss = sstar, na = snabove, ne = sneq;

    int running_eq = 0;
    for (int base = 0; base < NL; base += blockDim.x) {
        int l = base + tid;
        int s = (l < NL) ? sc[l] : -1;
        bool pg = (s > ss);
        bool pe = (s == ss);
        if (pg) {
            int slot = atomicAdd(&cnt_above, 1);     // order fixed by final sort
            sel[slot] = ((80 - s) << 17) | l;
        }
        unsigned mask = __ballot_sync(0xffffffffu, pe);
        int wpre = __popc(mask & ((1u << lane) - 1u));
        if (lane == 0) warp_eq[wid] = __popc(mask);
        __syncthreads();
        int woff = 0, tot = 0;
        #pragma unroll
        for (int w = 0; w < 32; w++) { if (w < wid) woff += warp_eq[w]; tot += warp_eq[w]; }
        if (pe) {
            int rank = running_eq + woff + wpre;     // global index-order rank
            if (rank < ne) sel[na + rank] = ((80 - ss) << 17) | l;
        }
        running_eq += tot;
        __syncthreads();
    }
    if (tid >= NTOP && tid < 256) sel[tid] = 0x7FFFFFFF;
    __syncthreads();

    // bitonic sort 256 keys ascending -> (score desc, idx asc)
    for (int size = 2; size <= 256; size <<= 1) {
        for (int stride = size >> 1; stride > 0; stride >>= 1) {
            if (tid < 256) {
                int partner = tid ^ stride;
                if (partner > tid) {
                    bool up = ((tid & size) == 0);
                    int x = sel[tid], y = sel[partner];
                    if ((x > y) == up) { sel[tid] = y; sel[partner] = x; }
                }
            }
            __syncthreads();
        }
    }
    if (tid < NTOP) g_topidx[b * NTOP + tid] = sel[tid] & 0x1FFFF;
}

// ============================================================
// Kernel 3: candidate generation + scoring. Block = (k, b), thread = angle a.
// ============================================================
__global__ void k_cand(const float* __restrict__ peaks,
                       const float* __restrict__ cell,
                       const float* __restrict__ lat) {
    int k = blockIdx.x;
    int b = blockIdx.y;
    int a = threadIdx.x;  // 0..89

    __shared__ float sp[NPK * 3];
    __shared__ float s_cells[9], s_A[9], s_AA[9];

    for (int i = threadIdx.x; i < NPK * 3; i += blockDim.x)
        sp[i] = peaks[b * NPK * 3 + i];

    if (threadIdx.x == 0) {
        int li = g_topidx[b * NTOP + k];
        float tx = lat[li*3+0], ty = lat[li*3+1], tz = lat[li*3+2];
        // sn = normalize(cell[0]); tn = normalize(dir)  (with +EPS like ref)
        float c00=cell[0], c01=cell[1], c02=cell[2];
        float snn = sqrtf(c00*c00 + c01*c01 + c02*c02) + EPSF;
        float sx=c00/snn, sy=c01/snn, sz=c02/snn;
        float tnn = sqrtf(tx*tx + ty*ty + tz*tz) + EPSF;
        float ux=tx/tnn, uy=ty/tnn, uz=tz/tnn;
        float Vx = sy*uz - sz*uy;
        float Vy = sz*ux - sx*uz;
        float Vz = sx*uy - sy*ux;
        float C  = sx*ux + sy*uy + sz*uz;
        float S2 = Vx*Vx + Vy*Vy + Vz*Vz;
        float K[9]  = {0.0f,-Vz,Vy,  Vz,0.0f,-Vx,  -Vy,Vx,0.0f};
        float KK[9];
        #pragma unroll
        for (int r = 0; r < 3; r++)
            #pragma unroll
            for (int c2 = 0; c2 < 3; c2++)
                KK[r*3+c2] = K[r*3+0]*K[0*3+c2] + K[r*3+1]*K[1*3+c2] + K[r*3+2]*K[2*3+c2];
        float fac = (1.0f - C) / (S2 + EPSF);
        float R0[9];
        #pragma unroll
        for (int i = 0; i < 9; i++) {
            float Ii = (i == 0 || i == 4 || i == 8) ? 1.0f : 0.0f;
            R0[i] = (Ii + K[i]) + fac * KK[i];
        }
        // cells[r,i] = sum_j R0[i,j] * cell[r,j]
        #pragma unroll
        for (int r = 0; r < 3; r++)
            #pragma unroll
            for (int i = 0; i < 3; i++)
                s_cells[r*3+i] = R0[i*3+0]*cell[r*3+0] + R0[i*3+1]*cell[r*3+1] + R0[i*3+2]*cell[r*3+2];
        // rodrigues precomputation: A = skew(tn), AA = A@A
        float A2[9] = {0.0f,-uz,uy,  uz,0.0f,-ux,  -uy,ux,0.0f};
        #pragma unroll
        for (int i = 0; i < 9; i++) s_A[i] = A2[i];
        #pragma unroll
        for (int r = 0; r < 3; r++)
            #pragma unroll
            for (int c2 = 0; c2 < 3; c2++)
                s_AA[r*3+c2] = A2[r*3+0]*A2[0*3+c2] + A2[r*3+1]*A2[1*3+c2] + A2[r*3+2]*A2[2*3+c2];
    }
    __syncthreads();

    float alpha = (6.2831855f * (float)a) / 90.0f;   // f32 order of ops like jnp
    float sv = sinf(alpha);
    float cv = 1.0f - cosf(alpha);
    float Rr[9];
    #pragma unroll
    for (int i = 0; i < 9; i++) {
        float Ii = (i == 0 || i == 4 || i == 8) ? 1.0f : 0.0f;
        Rr[i] = (Ii + sv * s_A[i]) + cv * s_AA[i];
    }
    float cd[9];
    #pragma unroll
    for (int r = 0; r < 3; r++)
        #pragma unroll
        for (int i = 0; i < 3; i++)
            cd[r*3+i] = Rr[i*3+0]*s_cells[r*3+0] + Rr[i*3+1]*s_cells[r*3+1] + Rr[i*3+2]*s_cells[r*3+2];

    int m = k * NANG + a;
    float* gc = g_cand + ((size_t)b * NM + m) * 9;
    #pragma unroll
    for (int i = 0; i < 9; i++) gc[i] = cd[i];

    float iv[9];
    inv3(cd, iv);
    int cnt = 0;
    #pragma unroll 4
    for (int n = 0; n < NPK; n++) {
        float p0 = sp[n*3+0], p1 = sp[n*3+1], p2 = sp[n*3+2];
        float h0 = p0*iv[0] + p1*iv[3] + p2*iv[6];
        float h1 = p0*iv[1] + p1*iv[4] + p2*iv[7];
        float h2 = p0*iv[2] + p1*iv[5] + p2*iv[8];
        float e0 = fabsf(h0 - rintf(h0));
        float e1 = fabsf(h1 - rintf(h1));
        float e2 = fabsf(h2 - rintf(h2));
        float e = fmaxf(e0, fmaxf(e1, e2));
        cnt += (e < DIST) ? 1 : 0;
    }
    // argmax first-occurrence semantics: max count, then smallest m
    unsigned long long key = ((unsigned long long)(unsigned)cnt << 32)
                           | (unsigned long long)(0xFFFFFFFFu - (unsigned)m);
    atomicMax(&g_best[b], key);
}

// ============================================================
// Kernel 4: refinement (5 weighted-LS rounds) + penalization + output
// One warp per batch.
// ============================================================
__global__ void k_refine(const float* __restrict__ peaks,
                         const float* __restrict__ cell,
                         float* __restrict__ out, int out_size) {
    int b = blockIdx.x;
    int lane = threadIdx.x;
    __shared__ float sB[9], sI[9];
    __shared__ int scount;

    if (lane == 0) {
        unsigned long long key = g_best[b];
        scount = (int)(key >> 32);
        int m = (int)(0xFFFFFFFFu - (unsigned)(key & 0xFFFFFFFFull));
        const float* gc = g_cand + ((size_t)b * NM + m) * 9;
        for (int i = 0; i < 9; i++) sB[i] = gc[i];
    }
    __syncthreads();

    const float thrs[5] = {0.02f, 0.015375f, 0.01075f, 0.006125f, 0.0015f};
    for (int t = 0; t < 5; t++) {
        if (lane == 0) inv3(sB, sI);
        __syncthreads();
        float acc[18];
        #pragma unroll
        for (int i = 0; i < 18; i++) acc[i] = 0.0f;
        for (int n = lane; n < NPK; n += 32) {
            const float* p = peaks + (b * NPK + n) * 3;
            float p0 = p[0], p1 = p[1], p2 = p[2];
            float h0 = rintf(p0*sI[0] + p1*sI[3] + p2*sI[6]);
            float h1 = rintf(p0*sI[1] + p1*sI[4] + p2*sI[7]);
            float h2 = rintf(p0*sI[2] + p1*sI[5] + p2*sI[8]);
            float q0 = h0*sB[0] + h1*sB[3] + h2*sB[6] - p0;
            float q1 = h0*sB[1] + h1*sB[4] + h2*sB[7] - p1;
            float q2 = h0*sB[2] + h1*sB[5] + h2*sB[8] - p2;
            float resid = sqrtf(q0*q0 + q1*q1 + q2*q2);
            if (resid < thrs[t]) {
                acc[0]+=h0*h0; acc[1]+=h0*h1; acc[2]+=h0*h2;
                acc[3]+=h1*h0; acc[4]+=h1*h1; acc[5]+=h1*h2;
                acc[6]+=h2*h0; acc[7]+=h2*h1; acc[8]+=h2*h2;
                acc[9]+=h0*p0;  acc[10]+=h0*p1; acc[11]+=h0*p2;
                acc[12]+=h1*p0; acc[13]+=h1*p1; acc[14]+=h1*p2;
                acc[15]+=h2*p0; acc[16]+=h2*p1; acc[17]+=h2*p2;
            }
        }
        #pragma unroll
        for (int off = 16; off > 0; off >>= 1)
            #pragma unroll
            for (int i = 0; i < 18; i++)
                acc[i] += __shfl_down_sync(0xffffffffu, acc[i], off);
        if (lane == 0) {
            float XtX[9], XtY[9], IX[9];
            #pragma unroll
            for (int i = 0; i < 9; i++) { XtX[i] = acc[i]; XtY[i] = acc[9 + i]; }
            inv3(XtX, IX);
            #pragma unroll
            for (int r = 0; r < 3; r++)
                #pragma unroll
                for (int d2 = 0; d2 < 3; d2++)
                    sB[r*3+d2] = IX[r*3+0]*XtY[0*3+d2] + IX[r*3+1]*XtY[1*3+d2] + IX[r*3+2]*XtY[2*3+d2];
        }
        __syncthreads();
    }

    if (lane == 0) {
        float bn[3], cn[3], dc = 0.0f;
        for (int r = 0; r < 3; r++) {
            bn[r] = sqrtf(sB[r*3]*sB[r*3] + sB[r*3+1]*sB[r*3+1] + sB[r*3+2]*sB[r*3+2]);
            cn[r] = sqrtf(cell[r*3]*cell[r*3] + cell[r*3+1]*cell[r*3+1] + cell[r*3+2]*cell[r*3+2]);
            dc = fmaxf(dc, fabsf(bn[r] - cn[r]));
        }
        float Bn[9], Cn[9];
        for (int r = 0; r < 3; r++)
            for (int i = 0; i < 3; i++) {
                Bn[r*3+i] = sB[r*3+i] / (bn[r] + EPSF);
                Cn[r*3+i] = cell[r*3+i] / (cn[r] + EPSF);
            }
        const float todeg = 57.29577951308232f;
        float da = 0.0f;
        const int pi_[3] = {0, 0, 1};
        const int pj_[3] = {1, 2, 2};
        for (int q = 0; q < 3; q++) {
            int i = pi_[q], j = pj_[q];
            float db = Bn[i*3]*Bn[j*3] + Bn[i*3+1]*Bn[j*3+1] + Bn[i*3+2]*Bn[j*3+2];
            float dl = Cn[i*3]*Cn[j*3] + Cn[i*3+1]*Cn[j*3+1] + Cn[i*3+2]*Cn[j*3+2];
            db = fminf(fmaxf(db, -1.0f), 1.0f);
            dl = fminf(fmaxf(dl, -1.0f), 1.0f);
            float ab = acosf(db) * todeg;
            float ac = acosf(dl) * todeg;
            da = fmaxf(da, fabsf(ab - ac));
        }
        float pen = dc*dc*dc + da*da*da;

        for (int i = 0; i < 9; i++) out[b*9 + i] = sB[i];
        if (out_size >= 88) {
            out[72 + b] = (float)scount;
            out[80 + b] = pen;
        }
    }
}

extern "C" void kernel_launch(void* const* d_in, const int* in_sizes, int n_in,
                              void* d_out, int out_size) {
    const float* peaks = (const float*)d_in[0];
    const float* cell  = (const float*)d_in[1];
    const float* lat   = (const float*)d_in[2];
    float* out = (float*)d_out;

    k_score<<<(NL + 255) / 256, 256>>>(peaks, cell, lat);
    k_topk<<<NB, 1024>>>();
    dim3 g3(NTOP, NB);
    k_cand<<<g3, NANG>>>(peaks, cell, lat);
    k_refine<<<NB, 32>>>(peaks, cell, out, out_size);
}

// round 2
// speedup vs baseline: 1.8186x; 1.8186x over previous
#include <cuda_runtime.h>
#include <math.h>

#define NB    8
#define NPK   80
#define NL    100000
#define NTOP  200
#define NANG  90
#define NM    (NTOP*NANG)
#define DIST  0.2f
#define EPSF  1e-12f
#define BINS  81

// ---- scratch (no allocation allowed) ----
__device__ unsigned char      g_score[NB * NL];
__device__ int                g_hist[NB * BINS];       // zero-init; k_select consumes+rezeros
__device__ int                g_topidx[NB * NTOP];
__device__ float              g_cand[(size_t)NB * NM * 9];
__device__ unsigned long long g_best[NB];              // zero-init; k_refine consumes+rezeros

// cofactor inverse matching the JAX reference (zero matrix if |det|<1e-10)
__device__ __forceinline__ void inv3(const float* M, float* o) {
    float a=M[0],b=M[1],c=M[2],d=M[3],e=M[4],f=M[5],g=M[6],h=M[7],i=M[8];
    float det = a*(e*i-f*h) - b*(d*i-f*g) + c*(d*h-e*g);
    float invd = (fabsf(det) >= 1e-10f) ? (1.0f/det) : 0.0f;
    o[0]=(e*i-f*h)*invd; o[1]=(c*h-b*i)*invd; o[2]=(b*f-c*e)*invd;
    o[3]=(f*g-d*i)*invd; o[4]=(a*i-c*g)*invd; o[5]=(c*d-a*f)*invd;
    o[6]=(d*h-e*g)*invd; o[7]=(b*g-a*h)*invd; o[8]=(a*e-b*d)*invd;
}

// ============================================================
// Kernel 1: integer-ness score over sphere lattice + folded histogram
// ============================================================
__global__ void k_score(const float* __restrict__ peaks,
                        const float* __restrict__ cell,
                        const float* __restrict__ lat) {
    __shared__ __align__(16) float sp[NB * NPK * 3];
    __shared__ int shist[NB * BINS];
    int tid = threadIdx.x;
    for (int i = tid; i < NB * NPK * 3; i += blockDim.x) sp[i] = peaks[i];
    for (int i = tid; i < NB * BINS; i += blockDim.x) shist[i] = 0;
    __syncthreads();

    int l = blockIdx.x * blockDim.x + tid;
    bool act = (l < NL);
    float lx = 0.f, ly = 0.f, lz = 0.f;
    if (act) { lx = lat[l*3+0]; ly = lat[l*3+1]; lz = lat[l*3+2]; }
    float scale0 = sqrtf(cell[0]*cell[0] + cell[1]*cell[1] + cell[2]*cell[2]);

    for (int b = 0; b < NB; b++) {
        const float4* p4 = (const float4*)(sp + b * NPK * 3);
        int cnt = 0;
        #pragma unroll 5
        for (int j = 0; j < NPK/4; j++) {
            float4 A = p4[3*j+0], B = p4[3*j+1], C = p4[3*j+2];
            // peak 0: A.x A.y A.z   peak1: A.w B.x B.y
            // peak 2: B.z B.w C.x   peak3: C.y C.z C.w
            float t0 = A.x * lx; t0 = fmaf(A.y, ly, t0); t0 = fmaf(A.z, lz, t0);
            float t1 = A.w * lx; t1 = fmaf(B.x, ly, t1); t1 = fmaf(B.y, lz, t1);
            float t2 = B.z * lx; t2 = fmaf(B.w, ly, t2); t2 = fmaf(C.x, lz, t2);
            float t3 = C.y * lx; t3 = fmaf(C.z, ly, t3); t3 = fmaf(C.w, lz, t3);
            float p0 = t0 / scale0, p1 = t1 / scale0, p2 = t2 / scale0, p3 = t3 / scale0;
            cnt += (fabsf(p0 - rintf(p0)) < DIST) ? 1 : 0;
            cnt += (fabsf(p1 - rintf(p1)) < DIST) ? 1 : 0;
            cnt += (fabsf(p2 - rintf(p2)) < DIST) ? 1 : 0;
            cnt += (fabsf(p3 - rintf(p3)) < DIST) ? 1 : 0;
        }
        if (act) {
            g_score[b * NL + l] = (unsigned char)cnt;
            atomicAdd(&shist[b * BINS + cnt], 1);
        }
    }
    __syncthreads();
    for (int i = tid; i < NB * BINS; i += blockDim.x) {
        int v = shist[i];
        if (v) atomicAdd(&g_hist[i], v);
    }
}

// ============================================================
// Kernel 2: exact top-200 per batch (jax.lax.top_k tie semantics:
//   score descending, index ascending within equal scores)
// Two-pass chunked scan, one block scan, one bitonic sort.
// ============================================================
__global__ void k_select() {
    int b = blockIdx.x;
    int tid = threadIdx.x;
    int lane = tid & 31, wid = tid >> 5;
    __shared__ int sh[BINS];
    __shared__ int sel[256];
    __shared__ int warpsum[32];
    __shared__ int s_ss, s_na, s_ne, gtc;

    if (tid < BINS) { sh[tid] = g_hist[b * BINS + tid]; g_hist[b * BINS + tid] = 0; }
    if (tid == 0) gtc = 0;
    __syncthreads();
    if (tid == 0) {
        int cum = 0, na = 0, s;
        for (s = 80; s >= 0; s--) {
            na = cum;
            cum += sh[s];
            if (cum >= NTOP) break;
        }
        s_ss = s; s_na = na; s_ne = NTOP - na;
    }
    __syncthreads();
    int ss = s_ss, na = s_na, ne = s_ne;

    const unsigned* scw = (const unsigned*)(g_score + (size_t)b * NL);
    // thread t owns bytes [t*100, t*100+100) = words [t*25, t*25+25); only tid<1000 active
    bool own = (tid < 1000);

    int eqc = 0;
    if (own) {
        #pragma unroll 5
        for (int w = 0; w < 25; w++) {
            unsigned word = scw[tid * 25 + w];
            #pragma unroll
            for (int j = 0; j < 4; j++) {
                int s = (word >> (8 * j)) & 0xff;
                if (s > ss) {
                    int slot = atomicAdd(&gtc, 1);
                    sel[slot] = ((80 - s) << 17) | (tid * 100 + w * 4 + j);
                }
                eqc += (s == ss) ? 1 : 0;
            }
        }
    }
    // block exclusive scan of eqc
    int v = eqc;
    #pragma unroll
    for (int off = 1; off < 32; off <<= 1) {
        int u = __shfl_up_sync(0xffffffffu, v, off);
        if (lane >= off) v += u;
    }
    if (lane == 31) warpsum[wid] = v;
    __syncthreads();
    if (tid < 32) {
        int x = warpsum[tid], y = x;
        #pragma unroll
        for (int off = 1; off < 32; off <<= 1) {
            int u = __shfl_up_sync(0xffffffffu, x, off);
            if (tid >= off) x += u;
        }
        warpsum[tid] = x - y;  // exclusive
    }
    __syncthreads();
    int rank = warpsum[wid] + (v - eqc);

    if (own) {
        #pragma unroll 5
        for (int w = 0; w < 25; w++) {
            unsigned word = scw[tid * 25 + w];
            #pragma unroll
            for (int j = 0; j < 4; j++) {
                int s = (word >> (8 * j)) & 0xff;
                if (s == ss) {
                    if (rank < ne) sel[na + rank] = ((80 - ss) << 17) | (tid * 100 + w * 4 + j);
                    rank++;
                }
            }
        }
    }
    if (tid >= NTOP && tid < 256) sel[tid] = 0x7FFFFFFF;
    __syncthreads();

    // bitonic sort 256 ascending -> (score desc, idx asc)
    for (int size = 2; size <= 256; size <<= 1) {
        for (int stride = size >> 1; stride > 0; stride >>= 1) {
            if (tid < 256) {
                int partner = tid ^ stride;
                if (partner > tid) {
                    bool up = ((tid & size) == 0);
                    int x = sel[tid], y = sel[partner];
                    if ((x > y) == up) { sel[tid] = y; sel[partner] = x; }
                }
            }
            __syncthreads();
        }
    }
    if (tid < NTOP) g_topidx[b * NTOP + tid] = sel[tid] & 0x1FFFF;
}

// ============================================================
// Kernel 3: candidate generation + scoring. Block = (k,b), thread = angle.
// Setup computed redundantly per thread; ONE atomic per block.
// ============================================================
__global__ void k_cand(const float* __restrict__ peaks,
                       const float* __restrict__ cell,
                       const float* __restrict__ lat) {
    int k = blockIdx.x;
    int b = blockIdx.y;
    int a = threadIdx.x;  // 0..89

    __shared__ float sp[NPK * 3];
    __shared__ unsigned long long skey[NANG];

    for (int i = a; i < NPK * 3; i += NANG)
        sp[i] = peaks[b * NPK * 3 + i];

    // ---- per-k setup, computed redundantly by every thread (uniform) ----
    int li = g_topidx[b * NTOP + k];
    float tx = lat[li*3+0], ty = lat[li*3+1], tz = lat[li*3+2];
    float c00 = cell[0], c01 = cell[1], c02 = cell[2];
    float snn = sqrtf(c00*c00 + c01*c01 + c02*c02) + EPSF;
    float sx = c00/snn, sy = c01/snn, sz = c02/snn;
    float tnn = sqrtf(tx*tx + ty*ty + tz*tz) + EPSF;
    float ux = tx/tnn, uy = ty/tnn, uz = tz/tnn;
    float Vx = sy*uz - sz*uy;
    float Vy = sz*ux - sx*uz;
    float Vz = sx*uy - sy*ux;
    float C  = sx*ux + sy*uy + sz*uz;
    float S2 = Vx*Vx + Vy*Vy + Vz*Vz;
    float K[9] = {0.0f,-Vz,Vy,  Vz,0.0f,-Vx,  -Vy,Vx,0.0f};
    float KK[9];
    #pragma unroll
    for (int r = 0; r < 3; r++)
        #pragma unroll
        for (int c2 = 0; c2 < 3; c2++)
            KK[r*3+c2] = K[r*3+0]*K[0*3+c2] + K[r*3+1]*K[1*3+c2] + K[r*3+2]*K[2*3+c2];
    float fac = (1.0f - C) / (S2 + EPSF);
    float R0[9];
    #pragma unroll
    for (int i = 0; i < 9; i++) {
        float Ii = (i == 0 || i == 4 || i == 8) ? 1.0f : 0.0f;
        R0[i] = (Ii + K[i]) + fac * KK[i];
    }
    float cells[9];
    #pragma unroll
    for (int r = 0; r < 3; r++)
        #pragma unroll
        for (int i = 0; i < 3; i++)
            cells[r*3+i] = R0[i*3+0]*cell[r*3+0] + R0[i*3+1]*cell[r*3+1] + R0[i*3+2]*cell[r*3+2];
    float A2[9] = {0.0f,-uz,uy,  uz,0.0f,-ux,  -uy,ux,0.0f};
    float AA[9];
    #pragma unroll
    for (int r = 0; r < 3; r++)
        #pragma unroll
        for (int c2 = 0; c2 < 3; c2++)
            AA[r*3+c2] = A2[r*3+0]*A2[0*3+c2] + A2[r*3+1]*A2[1*3+c2] + A2[r*3+2]*A2[2*3+c2];

    // ---- per-angle candidate ----
    float alpha = (6.2831855f * (float)a) / 90.0f;
    float sv = sinf(alpha);
    float cv = 1.0f - cosf(alpha);
    float Rr[9];
    #pragma unroll
    for (int i = 0; i < 9; i++) {
        float Ii = (i == 0 || i == 4 || i == 8) ? 1.0f : 0.0f;
        Rr[i] = (Ii + sv * A2[i]) + cv * AA[i];
    }
    float cd[9];
    #pragma unroll
    for (int r = 0; r < 3; r++)
        #pragma unroll
        for (int i = 0; i < 3; i++)
            cd[r*3+i] = Rr[i*3+0]*cells[r*3+0] + Rr[i*3+1]*cells[r*3+1] + Rr[i*3+2]*cells[r*3+2];

    int m = k * NANG + a;
    float* gc = g_cand + ((size_t)b * NM + m) * 9;
    #pragma unroll
    for (int i = 0; i < 9; i++) gc[i] = cd[i];

    float iv[9];
    inv3(cd, iv);
    __syncthreads();  // sp ready
    int cnt = 0;
    #pragma unroll 4
    for (int n = 0; n < NPK; n++) {
        float p0 = sp[n*3+0], p1 = sp[n*3+1], p2 = sp[n*3+2];
        float h0 = p0*iv[0] + p1*iv[3] + p2*iv[6];
        float h1 = p0*iv[1] + p1*iv[4] + p2*iv[7];
        float h2 = p0*iv[2] + p1*iv[5] + p2*iv[8];
        float e0 = fabsf(h0 - rintf(h0));
        float e1 = fabsf(h1 - rintf(h1));
        float e2 = fabsf(h2 - rintf(h2));
        float e = fmaxf(e0, fmaxf(e1, e2));
        cnt += (e < DIST) ? 1 : 0;
    }
    // argmax first-occurrence: max count, then smallest m
    unsigned long long key = ((unsigned long long)(unsigned)cnt << 32)
                           | (unsigned long long)(0xFFFFFFFFu - (unsigned)m);
    skey[a] = key;
    __syncthreads();
    if (a < 32) {
        unsigned long long v = skey[a];
        if (a + 32 < NANG) { unsigned long long u = skey[a+32]; v = (u > v) ? u : v; }
        if (a + 64 < NANG) { unsigned long long u = skey[a+64]; v = (u > v) ? u : v; }
        #pragma unroll
        for (int off = 16; off > 0; off >>= 1) {
            unsigned long long u = __shfl_xor_sync(0xffffffffu, v, off);
            v = (u > v) ? u : v;
        }
        if (a == 0) atomicMax(&g_best[b], v);
    }
}

// ============================================================
// Kernel 4: 5-round weighted-LS refinement + penalization. One warp per batch.
// Peaks register-cached; butterfly reduce; redundant per-lane 3x3 algebra.
// ============================================================
__global__ void k_refine(const float* __restrict__ peaks,
                         const float* __restrict__ cell,
                         float* __restrict__ out, int out_size) {
    int b = blockIdx.x;
    int lane = threadIdx.x;

    unsigned long long key = g_best[b];
    int scount = (int)(key >> 32);
    int m = (int)(0xFFFFFFFFu - (unsigned)(key & 0xFFFFFFFFull));
    const float* gc = g_cand + ((size_t)b * NM + m) * 9;
    float B[9];
    #pragma unroll
    for (int i = 0; i < 9; i++) B[i] = gc[i];

    // preload this lane's peaks (n = lane, lane+32, lane+64)
    float Px[3], Py[3], Pz[3];
    bool pv[3];
    #pragma unroll
    for (int r = 0; r < 3; r++) {
        int n = lane + 32 * r;
        pv[r] = (n < NPK);
        if (pv[r]) {
            const float* p = peaks + (b * NPK + n) * 3;
            Px[r] = p[0]; Py[r] = p[1]; Pz[r] = p[2];
        } else { Px[r] = Py[r] = Pz[r] = 0.f; }
    }

    const float thrs[5] = {0.02f, 0.015375f, 0.01075f, 0.006125f, 0.0015f};
    #pragma unroll
    for (int t = 0; t < 5; t++) {
        float I[9];
        inv3(B, I);
        float acc[18];
        #pragma unroll
        for (int i = 0; i < 18; i++) acc[i] = 0.0f;
        #pragma unroll
        for (int r = 0; r < 3; r++) {
            if (pv[r]) {
                float p0 = Px[r], p1 = Py[r], p2 = Pz[r];
                float h0 = rintf(p0*I[0] + p1*I[3] + p2*I[6]);
                float h1 = rintf(p0*I[1] + p1*I[4] + p2*I[7]);
                float h2 = rintf(p0*I[2] + p1*I[5] + p2*I[8]);
                float q0 = h0*B[0] + h1*B[3] + h2*B[6] - p0;
                float q1 = h0*B[1] + h1*B[4] + h2*B[7] - p1;
                float q2 = h0*B[2] + h1*B[5] + h2*B[8] - p2;
                float resid = sqrtf(q0*q0 + q1*q1 + q2*q2);
                if (resid < thrs[t]) {
                    acc[0]+=h0*h0; acc[1]+=h0*h1; acc[2]+=h0*h2;
                    acc[3]+=h1*h0; acc[4]+=h1*h1; acc[5]+=h1*h2;
                    acc[6]+=h2*h0; acc[7]+=h2*h1; acc[8]+=h2*h2;
                    acc[9]+=h0*p0;  acc[10]+=h0*p1; acc[11]+=h0*p2;
                    acc[12]+=h1*p0; acc[13]+=h1*p1; acc[14]+=h1*p2;
                    acc[15]+=h2*p0; acc[16]+=h2*p1; acc[17]+=h2*p2;
                }
            }
        }
        #pragma unroll
        for (int off = 16; off > 0; off >>= 1)
            #pragma unroll
            for (int i = 0; i < 18; i++)
                acc[i] += __shfl_xor_sync(0xffffffffu, acc[i], off);
        // all lanes hold full sums -> redundant update (no barriers)
        float IX[9];
        inv3(acc, IX);
        float nB[9];
        #pragma unroll
        for (int r = 0; r < 3; r++)
            #pragma unroll
            for (int d2 = 0; d2 < 3; d2++)
                nB[r*3+d2] = IX[r*3+0]*acc[9+0*3+d2] + IX[r*3+1]*acc[9+1*3+d2] + IX[r*3+2]*acc[9+2*3+d2];
        #pragma unroll
        for (int i = 0; i < 9; i++) B[i] = nB[i];
    }

    if (lane == 0) {
        float bn[3], cn[3], dc = 0.0f;
        for (int r = 0; r < 3; r++) {
            bn[r] = sqrtf(B[r*3]*B[r*3] + B[r*3+1]*B[r*3+1] + B[r*3+2]*B[r*3+2]);
            cn[r] = sqrtf(cell[r*3]*cell[r*3] + cell[r*3+1]*cell[r*3+1] + cell[r*3+2]*cell[r*3+2]);
            dc = fmaxf(dc, fabsf(bn[r] - cn[r]));
        }
        float Bn[9], Cn[9];
        for (int r = 0; r < 3; r++)
            for (int i = 0; i < 3; i++) {
                Bn[r*3+i] = B[r*3+i] / (bn[r] + EPSF);
                Cn[r*3+i] = cell[r*3+i] / (cn[r] + EPSF);
            }
        const float todeg = 57.29577951308232f;
        float da = 0.0f;
        const int pi_[3] = {0, 0, 1};
        const int pj_[3] = {1, 2, 2};
        for (int q = 0; q < 3; q++) {
            int i = pi_[q], j = pj_[q];
            float db = Bn[i*3]*Bn[j*3] + Bn[i*3+1]*Bn[j*3+1] + Bn[i*3+2]*Bn[j*3+2];
            float dl = Cn[i*3]*Cn[j*3] + Cn[i*3+1]*Cn[j*3+1] + Cn[i*3+2]*Cn[j*3+2];
            db = fminf(fmaxf(db, -1.0f), 1.0f);
            dl = fminf(fmaxf(dl, -1.0f), 1.0f);
            float ab = acosf(db) * todeg;
            float ac = acosf(dl) * todeg;
            da = fmaxf(da, fabsf(ab - ac));
        }
        float pen = dc*dc*dc + da*da*da;

        for (int i = 0; i < 9; i++) out[b*9 + i] = B[i];
        if (out_size >= 88) {
            out[72 + b] = (float)scount;
            out[80 + b] = pen;
        }
        g_best[b] = 0ull;   // restore invariant for next graph replay
    }
}

extern "C" void kernel_launch(void* const* d_in, const int* in_sizes, int n_in,
                              void* d_out, int out_size) {
    const float* peaks = (const float*)d_in[0];
    const float* cell  = (const float*)d_in[1];
    const float* lat   = (const float*)d_in[2];
    float* out = (float*)d_out;

    k_score<<<(NL + 255) / 256, 256>>>(peaks, cell, lat);
    k_select<<<NB, 1024>>>();
    dim3 g3(NTOP, NB);
    k_cand<<<g3, NANG>>>(peaks, cell, lat);
    k_refine<<<NB, 32>>>(peaks, cell, out, out_size);
}

// round 4
// speedup vs baseline: 3.2047x; 1.7622x over previous
#include <cuda_runtime.h>
#include <math.h>

#define NB    8
#define NPK   80
#define NL    100000
#define NTOP  200
#define NANG  90
#define NM    (NTOP*NANG)
#define DIST  0.2f
#define EPSF  1e-12f
#define BINS  81

typedef unsigned long long ull;

// ---- scratch (no allocation allowed) ----
__device__ unsigned char g_score[NB * NL + 128];   // padded for uint4 overread
__device__ int           g_hist[NB * BINS];        // zero-init; k_select consumes+rezeros
__device__ int           g_topidx[NB * NTOP];
__device__ ull           g_key[NB * NTOP];         // per-(b,k) best (cnt, ~m) key

// packed f32x2 helpers (elementwise IEEE RN -> bit-identical to scalar)
#define MUL2(d,a,b)   asm("mul.rn.f32x2 %0,%1,%2;"    : "=l"(d) : "l"(a),"l"(b))
#define FMA2(d,a,b,c) asm("fma.rn.f32x2 %0,%1,%2,%3;" : "=l"(d) : "l"(a),"l"(b),"l"(c))
__device__ __forceinline__ ull pk2(float lo, float hi) {
    ull r; asm("mov.b64 %0,{%1,%2};" : "=l"(r) : "f"(lo), "f"(hi)); return r;
}
__device__ __forceinline__ float2 upk2(ull v) {
    float2 r; asm("mov.b64 {%0,%1},%2;" : "=f"(r.x), "=f"(r.y) : "l"(v)); return r;
}

// cofactor inverse matching the JAX reference (zero matrix if |det|<1e-10)
__device__ __forceinline__ void inv3(const float* M, float* o) {
    float a=M[0],b=M[1],c=M[2],d=M[3],e=M[4],f=M[5],g=M[6],h=M[7],i=M[8];
    float det = a*(e*i-f*h) - b*(d*i-f*g) + c*(d*h-e*g);
    float invd = (fabsf(det) >= 1e-10f) ? (1.0f/det) : 0.0f;
    o[0]=(e*i-f*h)*invd; o[1]=(c*h-b*i)*invd; o[2]=(b*f-c*e)*invd;
    o[3]=(f*g-d*i)*invd; o[4]=(a*i-c*g)*invd; o[5]=(c*d-a*f)*invd;
    o[6]=(d*h-e*g)*invd; o[7]=(b*g-a*h)*invd; o[8]=(a*e-b*d)*invd;
}

// candidate 3x3 from (direction, angle index) — used by k_cand and k_refine
__device__ __forceinline__ void make_cand(const float* __restrict__ cell,
                                          float tx, float ty, float tz,
                                          int a, float* cd) {
    float c00 = cell[0], c01 = cell[1], c02 = cell[2];
    float snn = sqrtf(c00*c00 + c01*c01 + c02*c02) + EPSF;
    float sx = c00/snn, sy = c01/snn, sz = c02/snn;
    float tnn = sqrtf(tx*tx + ty*ty + tz*tz) + EPSF;
    float ux = tx/tnn, uy = ty/tnn, uz = tz/tnn;
    float Vx = sy*uz - sz*uy;
    float Vy = sz*ux - sx*uz;
    float Vz = sx*uy - sy*ux;
    float C  = sx*ux + sy*uy + sz*uz;
    float S2 = Vx*Vx + Vy*Vy + Vz*Vz;
    float K[9] = {0.0f,-Vz,Vy,  Vz,0.0f,-Vx,  -Vy,Vx,0.0f};
    float KK[9];
    #pragma unroll
    for (int r = 0; r < 3; r++)
        #pragma unroll
        for (int c2 = 0; c2 < 3; c2++)
            KK[r*3+c2] = K[r*3+0]*K[0*3+c2] + K[r*3+1]*K[1*3+c2] + K[r*3+2]*K[2*3+c2];
    float fac = (1.0f - C) / (S2 + EPSF);
    float R0[9];
    #pragma unroll
    for (int i = 0; i < 9; i++) {
        float Ii = (i == 0 || i == 4 || i == 8) ? 1.0f : 0.0f;
        R0[i] = (Ii + K[i]) + fac * KK[i];
    }
    float cells[9];
    #pragma unroll
    for (int r = 0; r < 3; r++)
        #pragma unroll
        for (int i = 0; i < 3; i++)
            cells[r*3+i] = R0[i*3+0]*cell[r*3+0] + R0[i*3+1]*cell[r*3+1] + R0[i*3+2]*cell[r*3+2];
    float A2[9] = {0.0f,-uz,uy,  uz,0.0f,-ux,  -uy,ux,0.0f};
    float AA[9];
    #pragma unroll
    for (int r = 0; r < 3; r++)
        #pragma unroll
        for (int c2 = 0; c2 < 3; c2++)
            AA[r*3+c2] = A2[r*3+0]*A2[0*3+c2] + A2[r*3+1]*A2[1*3+c2] + A2[r*3+2]*A2[2*3+c2];
    float alpha = (6.2831855f * (float)a) / 90.0f;
    float sv = sinf(alpha);
    float cv = 1.0f - cosf(alpha);
    float Rr[9];
    #pragma unroll
    for (int i = 0; i < 9; i++) {
        float Ii = (i == 0 || i == 4 || i == 8) ? 1.0f : 0.0f;
        Rr[i] = (Ii + sv * A2[i]) + cv * AA[i];
    }
    #pragma unroll
    for (int r = 0; r < 3; r++)
        #pragma unroll
        for (int i = 0; i < 3; i++)
            cd[r*3+i] = Rr[i*3+0]*cells[r*3+0] + Rr[i*3+1]*cells[r*3+1] + Rr[i*3+2]*cells[r*3+2];
}

// ============================================================
// Kernel 1: integer-ness score over sphere lattice + folded histogram
// SoA peaks in shared; f32x2-packed dot + exact Markstein-2 division.
// ============================================================
__global__ void k_score(const float* __restrict__ peaks,
                        const float* __restrict__ cell,
                        const float* __restrict__ lat) {
    __shared__ __align__(8) float sx[NB * NPK];
    __shared__ __align__(8) float sy[NB * NPK];
    __shared__ __align__(8) float sz[NB * NPK];
    __shared__ int shist[NB * BINS];
    int tid = threadIdx.x;
    for (int i = tid; i < NB * NPK; i += blockDim.x) {
        int b = i / NPK, n = i % NPK;
        const float* p = peaks + (b * NPK + n) * 3;
        sx[i] = p[0]; sy[i] = p[1]; sz[i] = p[2];
    }
    for (int i = tid; i < NB * BINS; i += blockDim.x) shist[i] = 0;
    __syncthreads();

    int l = blockIdx.x * blockDim.x + tid;
    bool act = (l < NL);
    float lx = 0.f, ly = 0.f, lz = 0.f;
    if (act) { lx = lat[l*3+0]; ly = lat[l*3+1]; lz = lat[l*3+2]; }
    float scale0 = sqrtf(cell[0]*cell[0] + cell[1]*cell[1] + cell[2]*cell[2]);
    float rinv = 1.0f / scale0;               // correctly-rounded reciprocal
    ull LX = pk2(lx, lx), LY = pk2(ly, ly), LZ = pk2(lz, lz);
    ull RR = pk2(rinv, rinv), NS = pk2(-scale0, -scale0);

    for (int b = 0; b < NB; b++) {
        const ull* px = (const ull*)(sx + b * NPK);
        const ull* py = (const ull*)(sy + b * NPK);
        const ull* pz = (const ull*)(sz + b * NPK);
        int cnt = 0;
        #pragma unroll 8
        for (int j = 0; j < NPK/2; j++) {
            ull X = px[j], Y = py[j], Z = pz[j];
            ull t;  MUL2(t, X, LX); FMA2(t, Y, LY, t); FMA2(t, Z, LZ, t);
            // exact IEEE division t/scale0 via Markstein (2 refinements)
            ull q0; MUL2(q0, t, RR);
            ull e0; FMA2(e0, NS, q0, t);
            ull q1; FMA2(q1, RR, e0, q0);
            ull e1; FMA2(e1, NS, q1, t);
            ull q2; FMA2(q2, RR, e1, q1);
            float2 q = upk2(q2);
            float d0 = q.x - rintf(q.x);
            float d1 = q.y - rintf(q.y);
            cnt += (fabsf(d0) < DIST) ? 1 : 0;
            cnt += (fabsf(d1) < DIST) ? 1 : 0;
        }
        if (act) {
            g_score[b * NL + l] = (unsigned char)cnt;
            atomicAdd(&shist[b * BINS + cnt], 1);
        }
    }
    __syncthreads();
    for (int i = tid; i < NB * BINS; i += blockDim.x) {
        int v = shist[i];
        if (v) atomicAdd(&g_hist[i], v);
    }
}

// ============================================================
// Kernel 2: exact top-200 per batch (jax.lax.top_k tie semantics).
// 128B/thread ownership, uint4 loads, two passes, bitonic finish.
// ============================================================
__global__ void k_select() {
    int b = blockIdx.x;
    int tid = threadIdx.x;
    int lane = tid & 31, wid = tid >> 5;
    __shared__ int sh[BINS];
    __shared__ int sel[256];
    __shared__ int warpsum[32];
    __shared__ int s_ss, s_na, s_ne, gtc;

    if (tid < BINS) { sh[tid] = g_hist[b * BINS + tid]; g_hist[b * BINS + tid] = 0; }
    if (tid == 0) gtc = 0;
    __syncthreads();
    if (tid == 0) {
        int cum = 0, na = 0, s;
        for (s = 80; s >= 0; s--) {
            na = cum;
            cum += sh[s];
            if (cum >= NTOP) break;
        }
        s_ss = s; s_na = na; s_ne = NTOP - na;
    }
    __syncthreads();
    int ss = s_ss, na = s_na, ne = s_ne;

    const uint4* gp = (const uint4*)(g_score + (size_t)b * NL);
    bool own = (tid < 782);        // thread owns bytes [tid*128, tid*128+128)

    // pass A: collect ">ss" entries, count equals per thread
    int eqc = 0;
    if (own) {
        #pragma unroll
        for (int u = 0; u < 8; u++) {
            uint4 v = gp[tid * 8 + u];
            unsigned ws[4] = {v.x, v.y, v.z, v.w};
            #pragma unroll
            for (int w = 0; w < 4; w++) {
                #pragma unroll
                for (int j = 0; j < 4; j++) {
                    int idx = tid * 128 + u * 16 + w * 4 + j;
                    int s = (ws[w] >> (8 * j)) & 0xff;
                    if (idx < NL) {
                        if (s > ss) {
                            int slot = atomicAdd(&gtc, 1);
                            sel[slot] = ((80 - s) << 17) | idx;
                        }
                        eqc += (s == ss) ? 1 : 0;
                    }
                }
            }
        }
    }
    // block exclusive scan of eqc (ownership ranges are index-ordered)
    int v = eqc;
    #pragma unroll
    for (int off = 1; off < 32; off <<= 1) {
        int u = __shfl_up_sync(0xffffffffu, v, off);
        if (lane >= off) v += u;
    }
    if (lane == 31) warpsum[wid] = v;
    __syncthreads();
    if (tid < 32) {
        int x = warpsum[tid], y = x;
        #pragma unroll
        for (int off = 1; off < 32; off <<= 1) {
            int u = __shfl_up_sync(0xffffffffu, x, off);
            if (tid >= off) x += u;
        }
        warpsum[tid] = x - y;
    }
    __syncthreads();
    int rank = warpsum[wid] + (v - eqc);

    // pass B: place equals in global index order
    if (own && eqc > 0 && rank < ne) {
        #pragma unroll
        for (int u = 0; u < 8; u++) {
            uint4 vv = gp[tid * 8 + u];
            unsigned ws[4] = {vv.x, vv.y, vv.z, vv.w};
            #pragma unroll
            for (int w = 0; w < 4; w++) {
                #pragma unroll
                for (int j = 0; j < 4; j++) {
                    int idx = tid * 128 + u * 16 + w * 4 + j;
                    int s = (ws[w] >> (8 * j)) & 0xff;
                    if (idx < NL && s == ss) {
                        if (rank < ne) sel[na + rank] = ((80 - ss) << 17) | idx;
                        rank++;
                    }
                }
            }
        }
    }
    if (tid >= NTOP && tid < 256) sel[tid] = 0x7FFFFFFF;
    __syncthreads();

    // bitonic sort 256 ascending -> (score desc, idx asc)
    for (int size = 2; size <= 256; size <<= 1) {
        for (int stride = size >> 1; stride > 0; stride >>= 1) {
            if (tid < 256) {
                int partner = tid ^ stride;
                if (partner > tid) {
                    bool up = ((tid & size) == 0);
                    int x = sel[tid], y = sel[partner];
                    if ((x > y) == up) { sel[tid] = y; sel[partner] = x; }
                }
            }
            __syncthreads();
        }
    }
    if (tid < NTOP) g_topidx[b * NTOP + tid] = sel[tid] & 0x1FFFF;
}

// ============================================================
// Kernel 3: candidate scoring. Block=(k,b), thread=angle (96 thr, 90 real).
// Uniform barriers only. One packed key per (b,k), no atomics.
// ============================================================
__global__ void k_cand(const float* __restrict__ peaks,
                       const float* __restrict__ cell,
                       const float* __restrict__ lat) {
    int k = blockIdx.x;
    int b = blockIdx.y;
    int a = threadIdx.x;  // 0..95; lanes 90..95 compute garbage, key stays 0

    __shared__ float sp[NPK * 3];
    __shared__ ull skey[96];

    for (int i = a; i < NPK * 3; i += 96)
        sp[i] = peaks[b * NPK * 3 + i];

    int li = g_topidx[b * NTOP + k];
    float tx = lat[li*3+0], ty = lat[li*3+1], tz = lat[li*3+2];
    float cd[9];
    make_cand(cell, tx, ty, tz, a, cd);   // fine for a>=90 (unused)
    float iv[9];
    inv3(cd, iv);

    __syncthreads();  // sp ready — uniform barrier, all 96 threads

    int cnt = 0;
    #pragma unroll 4
    for (int n = 0; n < NPK; n++) {
        float p0 = sp[n*3+0], p1 = sp[n*3+1], p2 = sp[n*3+2];
        float h0 = p0*iv[0] + p1*iv[3] + p2*iv[6];
        float h1 = p0*iv[1] + p1*iv[4] + p2*iv[7];
        float h2 = p0*iv[2] + p1*iv[5] + p2*iv[8];
        float e0 = fabsf(h0 - rintf(h0));
        float e1 = fabsf(h1 - rintf(h1));
        float e2 = fabsf(h2 - rintf(h2));
        float e = fmaxf(e0, fmaxf(e1, e2));
        cnt += (e < DIST) ? 1 : 0;
    }
    int m = k * NANG + a;
    ull key = 0ull;
    if (a < NANG)
        key = ((ull)(unsigned)cnt << 32) | (ull)(0xFFFFFFFFu - (unsigned)m);
    skey[a] = key;

    __syncthreads();  // uniform barrier

    if (a < 32) {
        ull x = skey[a];
        ull y = skey[a + 32]; if (y > x) x = y;
        y = skey[a + 64]; if (y > x) x = y;
        #pragma unroll
        for (int off = 16; off > 0; off >>= 1) {
            ull u = __shfl_xor_sync(0xffffffffu, x, off);
            if (u > x) x = u;
        }
        if (a == 0) g_key[b * NTOP + k] = x;
    }
}

// ============================================================
// Kernel 4: reduce 200 keys, recompute winner, 5-round weighted LS,
// penalization, output. One warp per batch.
// ============================================================
__global__ void k_refine(const float* __restrict__ peaks,
                         const float* __restrict__ cell,
                         const float* __restrict__ lat,
                         float* __restrict__ out, int out_size) {
    int b = blockIdx.x;
    int lane = threadIdx.x;

    // max-reduce the 200 per-k keys
    ull best = 0ull;
    for (int k = lane; k < NTOP; k += 32) {
        ull u = g_key[b * NTOP + k];
        if (u > best) best = u;
    }
    #pragma unroll
    for (int off = 16; off > 0; off >>= 1) {
        ull u = __shfl_xor_sync(0xffffffffu, best, off);
        if (u > best) best = u;
    }
    int scount = (int)(best >> 32);
    int m = (int)(0xFFFFFFFFu - (unsigned)(best & 0xFFFFFFFFull));
    int kw = m / NANG, aw = m % NANG;

    // recompute the winning candidate matrix (all lanes, uniform)
    int li = g_topidx[b * NTOP + kw];
    float tx = lat[li*3+0], ty = lat[li*3+1], tz = lat[li*3+2];
    float B[9];
    make_cand(cell, tx, ty, tz, aw, B);

    // preload this lane's peaks (n = lane, lane+32, lane+64)
    float Px[3], Py[3], Pz[3];
    bool pv[3];
    #pragma unroll
    for (int r = 0; r < 3; r++) {
        int n = lane + 32 * r;
        pv[r] = (n < NPK);
        if (pv[r]) {
            const float* p = peaks + (b * NPK + n) * 3;
            Px[r] = p[0]; Py[r] = p[1]; Pz[r] = p[2];
        } else { Px[r] = Py[r] = Pz[r] = 0.f; }
    }

    const float thrs[5] = {0.02f, 0.015375f, 0.01075f, 0.006125f, 0.0015f};
    #pragma unroll
    for (int t = 0; t < 5; t++) {
        float I[9];
        inv3(B, I);
        float acc[18];
        #pragma unroll
        for (int i = 0; i < 18; i++) acc[i] = 0.0f;
        #pragma unroll
        for (int r = 0; r < 3; r++) {
            if (pv[r]) {
                float p0 = Px[r], p1 = Py[r], p2 = Pz[r];
                float h0 = rintf(p0*I[0] + p1*I[3] + p2*I[6]);
                float h1 = rintf(p0*I[1] + p1*I[4] + p2*I[7]);
                float h2 = rintf(p0*I[2] + p1*I[5] + p2*I[8]);
                float q0 = h0*B[0] + h1*B[3] + h2*B[6] - p0;
                float q1 = h0*B[1] + h1*B[4] + h2*B[7] - p1;
                float q2 = h0*B[2] + h1*B[5] + h2*B[8] - p2;
                float resid = sqrtf(q0*q0 + q1*q1 + q2*q2);
                if (resid < thrs[t]) {
                    acc[0]+=h0*h0; acc[1]+=h0*h1; acc[2]+=h0*h2;
                    acc[3]+=h1*h0; acc[4]+=h1*h1; acc[5]+=h1*h2;
                    acc[6]+=h2*h0; acc[7]+=h2*h1; acc[8]+=h2*h2;
                    acc[9]+=h0*p0;  acc[10]+=h0*p1; acc[11]+=h0*p2;
                    acc[12]+=h1*p0; acc[13]+=h1*p1; acc[14]+=h1*p2;
                    acc[15]+=h2*p0; acc[16]+=h2*p1; acc[17]+=h2*p2;
                }
            }
        }
        #pragma unroll
        for (int off = 16; off > 0; off >>= 1)
            #pragma unroll
            for (int i = 0; i < 18; i++)
                acc[i] += __shfl_xor_sync(0xffffffffu, acc[i], off);
        float IX[9];
        inv3(acc, IX);
        float nB[9];
        #pragma unroll
        for (int r = 0; r < 3; r++)
            #pragma unroll
            for (int d2 = 0; d2 < 3; d2++)
                nB[r*3+d2] = IX[r*3+0]*acc[9+0*3+d2] + IX[r*3+1]*acc[9+1*3+d2] + IX[r*3+2]*acc[9+2*3+d2];
        #pragma unroll
        for (int i = 0; i < 9; i++) B[i] = nB[i];
    }

    if (lane == 0) {
        float bn[3], cn[3], dc = 0.0f;
        for (int r = 0; r < 3; r++) {
            bn[r] = sqrtf(B[r*3]*B[r*3] + B[r*3+1]*B[r*3+1] + B[r*3+2]*B[r*3+2]);
            cn[r] = sqrtf(cell[r*3]*cell[r*3] + cell[r*3+1]*cell[r*3+1] + cell[r*3+2]*cell[r*3+2]);
            dc = fmaxf(dc, fabsf(bn[r] - cn[r]));
        }
        float Bn[9], Cn[9];
        for (int r = 0; r < 3; r++)
            for (int i = 0; i < 3; i++) {
                Bn[r*3+i] = B[r*3+i] / (bn[r] + EPSF);
                Cn[r*3+i] = cell[r*3+i] / (cn[r] + EPSF);
            }
        const float todeg = 57.29577951308232f;
        float da = 0.0f;
        const int pi_[3] = {0, 0, 1};
        const int pj_[3] = {1, 2, 2};
        for (int q = 0; q < 3; q++) {
            int i = pi_[q], j = pj_[q];
            float db = Bn[i*3]*Bn[j*3] + Bn[i*3+1]*Bn[j*3+1] + Bn[i*3+2]*Bn[j*3+2];
            float dl = Cn[i*3]*Cn[j*3] + Cn[i*3+1]*Cn[j*3+1] + Cn[i*3+2]*Cn[j*3+2];
            db = fminf(fmaxf(db, -1.0f), 1.0f);
            dl = fminf(fmaxf(dl, -1.0f), 1.0f);
            float ab = acosf(db) * todeg;
            float ac = acosf(dl) * todeg;
            da = fmaxf(da, fabsf(ab - ac));
        }
        float pen = dc*dc*dc + da*da*da;

        for (int i = 0; i < 9; i++) out[b*9 + i] = B[i];
        if (out_size >= 88) {
            out[72 + b] = (float)scount;
            out[80 + b] = pen;
        }
    }
}

extern "C" void kernel_launch(void* const* d_in, const int* in_sizes, int n_in,
                              void* d_out, int out_size) {
    const float* peaks = (const float*)d_in[0];
    const float* cell  = (const float*)d_in[1];
    const float* lat   = (const float*)d_in[2];
    float* out = (float*)d_out;

    k_score<<<(NL + 511) / 512, 512>>>(peaks, cell, lat);
    k_select<<<NB, 1024>>>();
    dim3 g3(NTOP, NB);
    k_cand<<<g3, 96>>>(peaks, cell, lat);
    k_refine<<<NB, 32>>>(peaks, cell, lat, out, out_size);
}